// round 7
// baseline (speedup 1.0000x reference)
#include <cuda_runtime.h>
#include <cuda_fp16.h>
#include <mma.h>
#include <math.h>
#include <stdint.h>

using namespace nvcuda;

// ---------------- problem constants ----------------
#define Dm 1024      // d_model
#define Hd 4096      // expert hidden
#define Ex 8         // experts
#define TK 2         // top-k
#define Bb 4
#define Ss 2048
#define Tt (Bb * Ss)         // 8192 tokens
#define PAIRS (Tt * TK)      // 16384
#define CAP 2560             // ceil(1.25 * T * K / E)

// ---------------- device scratch (no allocations allowed) ----------------
__device__ __half g_h  [(size_t)Ex * CAP * Hd];   // hidden acts (fp16)
__device__ float  g_eo [(size_t)Ex * CAP * Dm];   // expert outputs (fp32)
__device__ __half g_xh [(size_t)Tt * Dm];         // x in fp16
__device__ __half g_w1h[(size_t)Ex * Dm * Hd];    // W1 in fp16
__device__ __half g_w2h[(size_t)Ex * Hd * Dm];    // W2 in fp16
__device__ int    g_eid[PAIRS];
__device__ float  g_wp [PAIRS];
__device__ int    g_slot[PAIRS];
__device__ int    g_tok[Ex * CAP];
__device__ int    g_count[Ex];

// ---------------- helpers ----------------
__device__ __forceinline__ uint32_t smem_u32(const void* p) {
    uint32_t a;
    asm("{ .reg .u64 t; cvta.to.shared.u64 t, %1; cvt.u32.u64 %0, t; }" : "=r"(a) : "l"(p));
    return a;
}
__device__ __forceinline__ void cp16(uint32_t dst, const void* src) {
    asm volatile("cp.async.cg.shared.global [%0], [%1], 16;" :: "r"(dst), "l"(src));
}
#define CP_COMMIT() asm volatile("cp.async.commit_group;" ::: "memory")
#define CP_WAIT(n)  asm volatile("cp.async.wait_group %0;" :: "n"(n) : "memory")

// ---------------- router: warp per token ----------------
__global__ void router_kernel(const float* __restrict__ x,
                              const float* __restrict__ Wr)
{
    int warp = (blockIdx.x * blockDim.x + threadIdx.x) >> 5;
    int lane = threadIdx.x & 31;
    if (warp >= Tt) return;
    const float* xr = x + (size_t)warp * Dm;

    float acc[8];
#pragma unroll
    for (int e = 0; e < 8; e++) acc[e] = 0.f;
    for (int d = lane; d < Dm; d += 32) {
        float xv = __ldg(xr + d);
        const float4 a = *(const float4*)(Wr + d * 8);
        const float4 b = *(const float4*)(Wr + d * 8 + 4);
        acc[0] += xv * a.x; acc[1] += xv * a.y; acc[2] += xv * a.z; acc[3] += xv * a.w;
        acc[4] += xv * b.x; acc[5] += xv * b.y; acc[6] += xv * b.z; acc[7] += xv * b.w;
    }
#pragma unroll
    for (int e = 0; e < 8; e++)
#pragma unroll
        for (int off = 16; off > 0; off >>= 1)
            acc[e] += __shfl_xor_sync(0xFFFFFFFFu, acc[e], off);
    if (lane == 0) {
        int e0 = 0; float l0 = acc[0];
#pragma unroll
        for (int e = 1; e < 8; e++) if (acc[e] > l0) { l0 = acc[e]; e0 = e; }
        int e1 = -1; float l1 = -3.4e38f;
#pragma unroll
        for (int e = 0; e < 8; e++) {
            if (e == e0) continue;
            if (acc[e] > l1) { l1 = acc[e]; e1 = e; }
        }
        float w0 = 1.0f / (1.0f + __expf(l1 - l0));
        g_eid[2 * warp + 0] = e0;  g_eid[2 * warp + 1] = e1;
        g_wp [2 * warp + 0] = w0;  g_wp [2 * warp + 1] = 1.0f - w0;
    }
}

// ---------------- exact ordered capacity dispatch (single block) ----------------
__global__ void scan_kernel()
{
    __shared__ int sc[8][1024];
    int tid = threadIdx.x;
    int base = tid * 16;

    int le[16]; int lc[8];
#pragma unroll
    for (int e = 0; e < 8; e++) lc[e] = 0;
#pragma unroll
    for (int i = 0; i < 16; i++) { le[i] = g_eid[base + i]; lc[le[i]]++; }
#pragma unroll
    for (int e = 0; e < 8; e++) sc[e][tid] = lc[e];
    __syncthreads();
    for (int off = 1; off < 1024; off <<= 1) {
        int v[8];
#pragma unroll
        for (int e = 0; e < 8; e++) v[e] = (tid >= off) ? sc[e][tid - off] : 0;
        __syncthreads();
#pragma unroll
        for (int e = 0; e < 8; e++) sc[e][tid] += v[e];
        __syncthreads();
    }
    int pos[8];
#pragma unroll
    for (int e = 0; e < 8; e++) pos[e] = sc[e][tid] - lc[e];
#pragma unroll
    for (int i = 0; i < 16; i++) {
        int e = le[i]; int p = pos[e]++; int pr = base + i;
        if (p < CAP) { int s = e * CAP + p; g_slot[pr] = s; g_tok[s] = pr >> 1; }
        else g_slot[pr] = -1;
    }
    if (tid < 8) { int c = sc[tid][1023]; g_count[tid] = (c < CAP) ? c : CAP; }
}

// ---------------- f32 -> f16 conversion (one-shot, vectorized x8) ----------------
__global__ void f2h_kernel(const float* __restrict__ src, __half* __restrict__ dst,
                           size_t n8)
{
    size_t i = (size_t)blockIdx.x * blockDim.x + threadIdx.x;
    size_t stride = (size_t)gridDim.x * blockDim.x;
    for (; i < n8; i += stride) {
        float4 a = ((const float4*)src)[2 * i + 0];
        float4 b = ((const float4*)src)[2 * i + 1];
        __half2 h[4];
        h[0] = __floats2half2_rn(a.x, a.y);
        h[1] = __floats2half2_rn(a.z, a.w);
        h[2] = __floats2half2_rn(b.x, b.y);
        h[3] = __floats2half2_rn(b.z, b.w);
        ((uint4*)dst)[i] = *(uint4*)h;
    }
}

// ---------------- GELU (tanh approx, matches jax.nn.gelu) ----------------
__device__ __forceinline__ float gelu_tanh(float v)
{
    float c = 0.7978845608028654f * (v + 0.044715f * v * v * v);
    return 0.5f * v * (1.0f + tanhf(c));
}

// ---------------- wmma fp16 expert GEMM, BM=128 BN=256 ----------------
// C[128x256] = act( A @ B + bias ),  A:[M][K] fp16 row-major (gathered),
// B:[K][N] fp16 row-major. 512 threads / 16 warps, warp grid 4x4,
// warp tile 32x64, wmma 16x16x16 half, fp32 accum, BK=64, 3-stage cp.async.
template <int Kdim, int Ndim, bool GELU, bool GATHER>
__global__ void __launch_bounds__(512, 1)
expert_wmma(const __half* __restrict__ Ax,
            const __half* __restrict__ Bw,
            const float* __restrict__ bias)
{
    constexpr int BM = 128, BN = 256, BK = 64, NS = 3;
    constexpr int MT = CAP / BM;              // 20 row tiles / expert
    constexpr int ASTh = BK + 8;              // 72 halfs (144 B)
    constexpr int BSTh = BN + 8;              // 264 halfs (528 B)
    constexpr int ABYTES = BM * ASTh * 2;     // 18432
    constexpr int BBYTES = BK * BSTh * 2;     // 33792
    constexpr int STAGE  = ABYTES + BBYTES;   // 52224
    constexpr int CST = BN + 4;               // 260 floats

    extern __shared__ __align__(16) char smem[];
    int*   srow = (int*)smem;                  // 512 B
    float* sC   = (float*)(smem + 512);        // reused after mainloop (133120 B)
    char*  stg  = smem + 512;
    const uint32_t stg_u = smem_u32(stg);

    const int e   = blockIdx.y / MT;
    const int m0  = (blockIdx.y % MT) * BM;
    const int cnt = g_count[e];
    if (m0 >= cnt) return;
    const int n0  = blockIdx.x * BN;
    const int tid = threadIdx.x;
    const int wid = tid >> 5;

    if (tid < BM) {
        int r = m0 + tid;
        srow[tid] = (r < cnt) ? (GATHER ? g_tok[e * CAP + r] : e * CAP + r)
                              : (GATHER ? 0 : e * CAP);
    }
    __syncthreads();

    const __half* Asrc = GATHER ? Ax : (const __half*)g_h;
    const __half* Bexp = Bw + (size_t)e * Kdim * Ndim + n0;

    // A: 128 rows x 64 halfs = 1024 x 16B chunks; 512 thr -> 2 each.
    // chunk = tid + l*512 -> row = chunk>>3, c8 = chunk&7
    const int ar0 = tid >> 3, ac8 = tid & 7;
    int arows[2];
#pragma unroll
    for (int l = 0; l < 2; l++) arows[l] = srow[ar0 + l * 64];
    // B: 64 rows x 256 halfs = 2048 chunks; 4 each. row = chunk>>5, c8 = chunk&31
    const int br0 = tid >> 5, bc8 = tid & 31;

    auto load_stage = [&](int s, int k0) {
        uint32_t sA = stg_u + s * STAGE;
        uint32_t sB = sA + ABYTES;
#pragma unroll
        for (int l = 0; l < 2; l++) {
            int row = ar0 + l * 64;
            cp16(sA + (uint32_t)(row * (ASTh * 2) + ac8 * 16),
                 Asrc + (size_t)arows[l] * Kdim + k0 + ac8 * 8);
        }
#pragma unroll
        for (int l = 0; l < 4; l++) {
            int row = br0 + l * 16;
            cp16(sB + (uint32_t)(row * (BSTh * 2) + bc8 * 16),
                 Bexp + (size_t)(k0 + row) * Ndim + bc8 * 8);
        }
        CP_COMMIT();
    };

    const int warp_m = wid >> 2;     // 0..3 -> M offset warp_m*32
    const int warp_n = wid & 3;      // 0..3 -> N offset warp_n*64

    wmma::fragment<wmma::accumulator, 16, 16, 16, float> acc[2][4];
#pragma unroll
    for (int i = 0; i < 2; i++)
#pragma unroll
        for (int j = 0; j < 4; j++) wmma::fill_fragment(acc[i][j], 0.f);

    constexpr int KT = Kdim / BK;
    load_stage(0, 0);
    load_stage(1, BK);

    int cs = 0;
    for (int j = 0; j < KT; j++) {
        if (j + 2 < KT) CP_WAIT(1); else CP_WAIT(0);
        __syncthreads();
        if (j + 2 < KT) {
            int ls = cs + 2; if (ls >= NS) ls -= NS;
            load_stage(ls, (j + 2) * BK);
        }

        const __half* sA = (const __half*)(stg + cs * STAGE);
        const __half* sB = (const __half*)(stg + cs * STAGE + ABYTES);

#pragma unroll
        for (int ks = 0; ks < BK / 16; ks++) {
            wmma::fragment<wmma::matrix_a, 16, 16, 16, __half, wmma::row_major> af[2];
#pragma unroll
            for (int i = 0; i < 2; i++)
                wmma::load_matrix_sync(af[i], sA + (warp_m * 32 + i * 16) * ASTh + ks * 16, ASTh);
            // stream B fragments one at a time to bound register pressure
#pragma unroll
            for (int jn = 0; jn < 4; jn++) {
                wmma::fragment<wmma::matrix_b, 16, 16, 16, __half, wmma::row_major> bf;
                wmma::load_matrix_sync(bf, sB + (ks * 16) * BSTh + warp_n * 64 + jn * 16, BSTh);
#pragma unroll
                for (int i = 0; i < 2; i++)
                    wmma::mma_sync(acc[i][jn], af[i], bf, acc[i][jn]);
            }
        }
        cs++; if (cs >= NS) cs = 0;
    }

    __syncthreads();   // all warps done with stages before sC overwrite

#pragma unroll
    for (int i = 0; i < 2; i++)
#pragma unroll
        for (int jn = 0; jn < 4; jn++)
            wmma::store_matrix_sync(sC + (warp_m * 32 + i * 16) * CST + warp_n * 64 + jn * 16,
                                    acc[i][jn], CST, wmma::mem_row_major);
    __syncthreads();

    // epilogue: 4 threads per row, 64 cols each
    {
        const int row  = tid >> 2;
        const int col0 = (tid & 3) * 64;
        const int r = m0 + row;
        if (r < cnt) {
            const float* bv = bias + e * Ndim + n0 + col0;
            const float* src = sC + row * CST + col0;
            if (GELU) {
                __half* crow = (__half*)g_h + ((size_t)(e * CAP + r)) * Ndim + n0 + col0;
#pragma unroll
                for (int c = 0; c < 64; c += 4) {
                    float4 v = *(const float4*)(src + c);
                    v.x = gelu_tanh(v.x + __ldg(bv + c + 0));
                    v.y = gelu_tanh(v.y + __ldg(bv + c + 1));
                    v.z = gelu_tanh(v.z + __ldg(bv + c + 2));
                    v.w = gelu_tanh(v.w + __ldg(bv + c + 3));
                    __half2 h0 = __floats2half2_rn(v.x, v.y);
                    __half2 h1 = __floats2half2_rn(v.z, v.w);
                    *(uint2*)(crow + c) = make_uint2(*(uint32_t*)&h0, *(uint32_t*)&h1);
                }
            } else {
                float* crow = g_eo + ((size_t)(e * CAP + r)) * Ndim + n0 + col0;
#pragma unroll
                for (int c = 0; c < 64; c += 4) {
                    float4 v = *(const float4*)(src + c);
                    v.x += __ldg(bv + c + 0);
                    v.y += __ldg(bv + c + 1);
                    v.z += __ldg(bv + c + 2);
                    v.w += __ldg(bv + c + 3);
                    *(float4*)(crow + c) = v;
                }
            }
        }
    }
}

// ---------------- combine: one block per token ----------------
__global__ void combine_kernel(float* __restrict__ out)
{
    int t = blockIdx.x;
    int c = threadIdx.x * 4;
    int   s0 = g_slot[2 * t + 0];
    int   s1 = g_slot[2 * t + 1];
    float w0 = g_wp[2 * t + 0];
    float w1 = g_wp[2 * t + 1];
    float4 r = make_float4(0.f, 0.f, 0.f, 0.f);
    if (s0 >= 0) {
        float4 a = *(const float4*)(g_eo + (size_t)s0 * Dm + c);
        r.x += w0 * a.x; r.y += w0 * a.y; r.z += w0 * a.z; r.w += w0 * a.w;
    }
    if (s1 >= 0) {
        float4 a = *(const float4*)(g_eo + (size_t)s1 * Dm + c);
        r.x += w1 * a.x; r.y += w1 * a.y; r.z += w1 * a.z; r.w += w1 * a.w;
    }
    *(float4*)(out + (size_t)t * Dm + c) = r;
}

// ---------------- entry point ----------------
extern "C" void kernel_launch(void* const* d_in, const int* in_sizes, int n_in,
                              void* d_out, int out_size)
{
    const float* x  = (const float*)d_in[0];
    const float* Wr = (const float*)d_in[1];
    const float* W1 = (const float*)d_in[2];
    const float* b1 = (const float*)d_in[3];
    const float* W2 = (const float*)d_in[4];
    const float* b2 = (const float*)d_in[5];
    float* out = (float*)d_out;

    // dynamic smem: 512 + 3 * 52224 = 157184 B
    constexpr int SMEM_SZ = 512 + 3 * 52224;
    static_assert(512 + 128 * (256 + 4) * 4 <= SMEM_SZ, "C reuse fits");
    cudaFuncSetAttribute((const void*)&expert_wmma<Dm, Hd, true,  true >,
                         cudaFuncAttributeMaxDynamicSharedMemorySize, SMEM_SZ);
    cudaFuncSetAttribute((const void*)&expert_wmma<Hd, Dm, false, false>,
                         cudaFuncAttributeMaxDynamicSharedMemorySize, SMEM_SZ);

    __half* xh;  cudaGetSymbolAddress((void**)&xh,  g_xh);
    __half* w1h; cudaGetSymbolAddress((void**)&w1h, g_w1h);
    __half* w2h; cudaGetSymbolAddress((void**)&w2h, g_w2h);

    // 1) router (full-precision x)
    router_kernel<<<Tt / 8, 256>>>(x, Wr);
    // 2) exact ordered capacity dispatch
    scan_kernel<<<1, 1024>>>();
    // 2b) one-shot fp32 -> fp16 conversions
    f2h_kernel<<<1024, 256>>>(x,  xh,  (size_t)Tt * Dm / 8);
    f2h_kernel<<<2048, 256>>>(W1, w1h, (size_t)Ex * Dm * Hd / 8);
    f2h_kernel<<<2048, 256>>>(W2, w2h, (size_t)Ex * Hd * Dm / 8);
    // 3) GEMM1 + GELU: xh[gather] @ W1h + b1 -> g_h (fp16)
    expert_wmma<Dm, Hd, true,  true ><<<dim3(Hd / 256, Ex * (CAP / 128)), 512, SMEM_SZ>>>(xh, w1h, b1);
    // 4) GEMM2: g_h @ W2h + b2 -> g_eo (fp32)
    expert_wmma<Hd, Dm, false, false><<<dim3(Dm / 256, Ex * (CAP / 128)), 512, SMEM_SZ>>>(nullptr, w2h, b2);
    // 5) combine
    combine_kernel<<<Tt, 256>>>(out);
}

// round 9
// speedup vs baseline: 1.0914x; 1.0914x over previous
#include <cuda_runtime.h>
#include <cuda_fp16.h>
#include <mma.h>
#include <math.h>
#include <stdint.h>

using namespace nvcuda;

// ---------------- problem constants ----------------
#define Dm 1024      // d_model
#define Hd 4096      // expert hidden
#define Ex 8         // experts
#define TK 2         // top-k
#define Bb 4
#define Ss 2048
#define Tt (Bb * Ss)         // 8192 tokens
#define PAIRS (Tt * TK)      // 16384
#define CAP 2560             // ceil(1.25 * T * K / E)

// ---------------- device scratch (no allocations allowed) ----------------
__device__ __half g_h  [(size_t)Ex * CAP * Hd];   // hidden acts (fp16)
__device__ __half g_xh [(size_t)Tt * Dm];         // x in fp16
__device__ __half g_w1h[(size_t)Ex * Dm * Hd];    // W1 in fp16
__device__ __half g_w2h[(size_t)Ex * Hd * Dm];    // W2 in fp16
__device__ int    g_eid[PAIRS];
__device__ float  g_wp [PAIRS];
__device__ int    g_tok[Ex * CAP];                // token per slot
__device__ float  g_wslot[Ex * CAP];              // gate weight per slot
__device__ int    g_count[Ex];

// ---------------- helpers ----------------
__device__ __forceinline__ uint32_t smem_u32(const void* p) {
    uint32_t a;
    asm("{ .reg .u64 t; cvta.to.shared.u64 t, %1; cvt.u32.u64 %0, t; }" : "=r"(a) : "l"(p));
    return a;
}
__device__ __forceinline__ void cp16(uint32_t dst, const void* src) {
    asm volatile("cp.async.cg.shared.global [%0], [%1], 16;" :: "r"(dst), "l"(src));
}
#define CP_COMMIT() asm volatile("cp.async.commit_group;" ::: "memory")
#define CP_WAIT(n)  asm volatile("cp.async.wait_group %0;" :: "n"(n) : "memory")

// ---------------- zero output ----------------
__global__ void zero_kernel(float* __restrict__ p, size_t n4)
{
    size_t i = (size_t)blockIdx.x * blockDim.x + threadIdx.x;
    size_t stride = (size_t)gridDim.x * blockDim.x;
    for (; i < n4; i += stride)
        ((float4*)p)[i] = make_float4(0.f, 0.f, 0.f, 0.f);
}

// ---------------- router: warp per token (also emits x in fp16) ----------------
__global__ void router_kernel(const float* __restrict__ x,
                              const float* __restrict__ Wr)
{
    int warp = (blockIdx.x * blockDim.x + threadIdx.x) >> 5;
    int lane = threadIdx.x & 31;
    if (warp >= Tt) return;
    const float* xr = x + (size_t)warp * Dm;
    __half* xh = (__half*)g_xh + (size_t)warp * Dm;   // device-side symbol access

    float acc[8];
#pragma unroll
    for (int e = 0; e < 8; e++) acc[e] = 0.f;
    for (int d = lane * 2; d < Dm; d += 64) {
        float2 xv = *(const float2*)(xr + d);
        *(__half2*)(xh + d) = __floats2half2_rn(xv.x, xv.y);
#pragma unroll
        for (int u = 0; u < 2; u++) {
            float xs = u ? xv.y : xv.x;
            const float4 a = *(const float4*)(Wr + (d + u) * 8);
            const float4 b = *(const float4*)(Wr + (d + u) * 8 + 4);
            acc[0] += xs * a.x; acc[1] += xs * a.y; acc[2] += xs * a.z; acc[3] += xs * a.w;
            acc[4] += xs * b.x; acc[5] += xs * b.y; acc[6] += xs * b.z; acc[7] += xs * b.w;
        }
    }
#pragma unroll
    for (int e = 0; e < 8; e++)
#pragma unroll
        for (int off = 16; off > 0; off >>= 1)
            acc[e] += __shfl_xor_sync(0xFFFFFFFFu, acc[e], off);
    if (lane == 0) {
        int e0 = 0; float l0 = acc[0];
#pragma unroll
        for (int e = 1; e < 8; e++) if (acc[e] > l0) { l0 = acc[e]; e0 = e; }
        int e1 = -1; float l1 = -3.4e38f;
#pragma unroll
        for (int e = 0; e < 8; e++) {
            if (e == e0) continue;
            if (acc[e] > l1) { l1 = acc[e]; e1 = e; }
        }
        float w0 = 1.0f / (1.0f + __expf(l1 - l0));
        g_eid[2 * warp + 0] = e0;  g_eid[2 * warp + 1] = e1;
        g_wp [2 * warp + 0] = w0;  g_wp [2 * warp + 1] = 1.0f - w0;
    }
}

// ---------------- exact ordered capacity dispatch (single block) ----------------
__global__ void scan_kernel()
{
    __shared__ int sc[8][1024];
    int tid = threadIdx.x;
    int base = tid * 16;

    int le[16]; int lc[8];
#pragma unroll
    for (int e = 0; e < 8; e++) lc[e] = 0;
#pragma unroll
    for (int i = 0; i < 16; i++) { le[i] = g_eid[base + i]; lc[le[i]]++; }
#pragma unroll
    for (int e = 0; e < 8; e++) sc[e][tid] = lc[e];
    __syncthreads();
    for (int off = 1; off < 1024; off <<= 1) {
        int v[8];
#pragma unroll
        for (int e = 0; e < 8; e++) v[e] = (tid >= off) ? sc[e][tid - off] : 0;
        __syncthreads();
#pragma unroll
        for (int e = 0; e < 8; e++) sc[e][tid] += v[e];
        __syncthreads();
    }
    int pos[8];
#pragma unroll
    for (int e = 0; e < 8; e++) pos[e] = sc[e][tid] - lc[e];
#pragma unroll
    for (int i = 0; i < 16; i++) {
        int e = le[i]; int p = pos[e]++; int pr = base + i;
        if (p < CAP) {
            int s = e * CAP + p;
            g_tok[s]   = pr >> 1;
            g_wslot[s] = g_wp[pr];
        }
    }
    if (tid < 8) { int c = sc[tid][1023]; g_count[tid] = (c < CAP) ? c : CAP; }
}

// ---------------- f32 -> f16 conversion (one-shot, vectorized x8) ----------------
__global__ void f2h_kernel(const float* __restrict__ src, __half* __restrict__ dst,
                           size_t n8)
{
    size_t i = (size_t)blockIdx.x * blockDim.x + threadIdx.x;
    size_t stride = (size_t)gridDim.x * blockDim.x;
    for (; i < n8; i += stride) {
        float4 a = ((const float4*)src)[2 * i + 0];
        float4 b = ((const float4*)src)[2 * i + 1];
        __half2 h[4];
        h[0] = __floats2half2_rn(a.x, a.y);
        h[1] = __floats2half2_rn(a.z, a.w);
        h[2] = __floats2half2_rn(b.x, b.y);
        h[3] = __floats2half2_rn(b.z, b.w);
        ((uint4*)dst)[i] = *(uint4*)h;
    }
}

// ---------------- GELU (tanh approx, matches jax.nn.gelu) ----------------
__device__ __forceinline__ float gelu_tanh(float v)
{
    float c = 0.7978845608028654f * (v + 0.044715f * v * v * v);
    return 0.5f * v * (1.0f + tanhf(c));
}

// ---------------- wmma fp16 expert GEMM (R6 config) ----------------
// C[128x128] = act( A @ B + bias ).  GELU=true: write fp16 g_h.
// GELU=false: scale rows by gate weight and atomically accumulate into out.
template <int Kdim, int Ndim, bool GELU, bool GATHER>
__global__ void __launch_bounds__(256, 2)
expert_wmma(const __half* __restrict__ Ax,
            const __half* __restrict__ Bw,
            const float* __restrict__ bias,
            float* __restrict__ out)
{
    constexpr int BM = 128, BN = 128, BK = 64, NS = 3;
    constexpr int MT = CAP / BM;              // 20 row tiles / expert
    constexpr int ASTh = BK + 8;              // 72 halfs
    constexpr int BSTh = BN + 8;              // 136 halfs
    constexpr int ABYTES = BM * ASTh * 2;     // 18432
    constexpr int BBYTES = BK * BSTh * 2;     // 17408
    constexpr int STAGE  = ABYTES + BBYTES;   // 35840
    constexpr int CST = BN + 4;

    extern __shared__ __align__(16) char smem[];
    int*   srow = (int*)smem;                  // 512 B
    float* sC   = (float*)(smem + 512);        // reused after mainloop
    char*  stg  = smem + 512;
    const uint32_t stg_u = smem_u32(stg);

    const int e   = blockIdx.y / MT;
    const int m0  = (blockIdx.y % MT) * BM;
    const int cnt = g_count[e];
    if (m0 >= cnt) return;
    const int n0  = blockIdx.x * BN;
    const int tid = threadIdx.x;
    const int wid = tid >> 5;

    if (tid < BM) {
        int r = m0 + tid;
        srow[tid] = (r < cnt) ? (GATHER ? g_tok[e * CAP + r] : e * CAP + r)
                              : (GATHER ? 0 : e * CAP);
    }
    __syncthreads();

    const __half* Asrc = GATHER ? Ax : (const __half*)g_h;
    const __half* Bexp = Bw + (size_t)e * Kdim * Ndim + n0;

    const int ar0 = tid >> 3, ac8 = tid & 7;
    int arows[4];
#pragma unroll
    for (int l = 0; l < 4; l++) arows[l] = srow[ar0 + l * 32];
    const int br0 = tid >> 4, bc8 = tid & 15;

    auto load_stage = [&](int s, int k0) {
        uint32_t sA = stg_u + s * STAGE;
        uint32_t sB = sA + ABYTES;
#pragma unroll
        for (int l = 0; l < 4; l++) {
            int row = ar0 + l * 32;
            cp16(sA + (uint32_t)(row * (ASTh * 2) + ac8 * 16),
                 Asrc + (size_t)arows[l] * Kdim + k0 + ac8 * 8);
        }
#pragma unroll
        for (int l = 0; l < 4; l++) {
            int row = br0 + l * 16;
            cp16(sB + (uint32_t)(row * (BSTh * 2) + bc8 * 16),
                 Bexp + (size_t)(k0 + row) * Ndim + bc8 * 8);
        }
        CP_COMMIT();
    };

    const int warp_m = wid >> 1;
    const int warp_n = wid & 1;

    wmma::fragment<wmma::accumulator, 16, 16, 16, float> acc[2][4];
#pragma unroll
    for (int i = 0; i < 2; i++)
#pragma unroll
        for (int j = 0; j < 4; j++) wmma::fill_fragment(acc[i][j], 0.f);

    constexpr int KT = Kdim / BK;
    load_stage(0, 0);
    load_stage(1, BK);

    int cs = 0;
    for (int j = 0; j < KT; j++) {
        if (j + 2 < KT) CP_WAIT(1); else CP_WAIT(0);
        __syncthreads();
        if (j + 2 < KT) {
            int ls = cs + 2; if (ls >= NS) ls -= NS;
            load_stage(ls, (j + 2) * BK);
        }

        const __half* sA = (const __half*)(stg + cs * STAGE);
        const __half* sB = (const __half*)(stg + cs * STAGE + ABYTES);

#pragma unroll
        for (int ks = 0; ks < BK / 16; ks++) {
            wmma::fragment<wmma::matrix_a, 16, 16, 16, __half, wmma::row_major> af[2];
            wmma::fragment<wmma::matrix_b, 16, 16, 16, __half, wmma::row_major> bf[4];
#pragma unroll
            for (int i = 0; i < 2; i++)
                wmma::load_matrix_sync(af[i], sA + (warp_m * 32 + i * 16) * ASTh + ks * 16, ASTh);
#pragma unroll
            for (int jn = 0; jn < 4; jn++)
                wmma::load_matrix_sync(bf[jn], sB + (ks * 16) * BSTh + warp_n * 64 + jn * 16, BSTh);
#pragma unroll
            for (int i = 0; i < 2; i++)
#pragma unroll
                for (int jn = 0; jn < 4; jn++)
                    wmma::mma_sync(acc[i][jn], af[i], bf[jn], acc[i][jn]);
        }
        cs++; if (cs >= NS) cs = 0;
    }

    __syncthreads();

#pragma unroll
    for (int i = 0; i < 2; i++)
#pragma unroll
        for (int jn = 0; jn < 4; jn++)
            wmma::store_matrix_sync(sC + (warp_m * 32 + i * 16) * CST + warp_n * 64 + jn * 16,
                                    acc[i][jn], CST, wmma::mem_row_major);
    __syncthreads();

    // epilogue: 2 threads per row, 64 cols each
    {
        const int row  = tid >> 1;
        const int col0 = (tid & 1) * 64;
        const int r = m0 + row;
        if (r < cnt) {
            const float* bv = bias + e * Ndim + n0 + col0;
            const float* src = sC + row * CST + col0;
            if (GELU) {
                __half* crow = (__half*)g_h + ((size_t)(e * CAP + r)) * Ndim + n0 + col0;
#pragma unroll
                for (int c = 0; c < 64; c += 4) {
                    float4 v = *(const float4*)(src + c);
                    v.x = gelu_tanh(v.x + __ldg(bv + c + 0));
                    v.y = gelu_tanh(v.y + __ldg(bv + c + 1));
                    v.z = gelu_tanh(v.z + __ldg(bv + c + 2));
                    v.w = gelu_tanh(v.w + __ldg(bv + c + 3));
                    __half2 h0 = __floats2half2_rn(v.x, v.y);
                    __half2 h1 = __floats2half2_rn(v.z, v.w);
                    *(uint2*)(crow + c) = make_uint2(*(uint32_t*)&h0, *(uint32_t*)&h1);
                }
            } else {
                // fused combine: out[token] += w * (C + b2); exactly 2 experts/token,
                // fp add is commutative -> deterministic result
                const int   t = g_tok[e * CAP + r];
                const float w = g_wslot[e * CAP + r];
                float* orow = out + (size_t)t * Ndim + n0 + col0;
#pragma unroll
                for (int c = 0; c < 64; c += 4) {
                    float4 v = *(const float4*)(src + c);
                    atomicAdd(orow + c + 0, w * (v.x + __ldg(bv + c + 0)));
                    atomicAdd(orow + c + 1, w * (v.y + __ldg(bv + c + 1)));
                    atomicAdd(orow + c + 2, w * (v.z + __ldg(bv + c + 2)));
                    atomicAdd(orow + c + 3, w * (v.w + __ldg(bv + c + 3)));
                }
            }
        }
    }
}

// ---------------- entry point ----------------
extern "C" void kernel_launch(void* const* d_in, const int* in_sizes, int n_in,
                              void* d_out, int out_size)
{
    const float* x  = (const float*)d_in[0];
    const float* Wr = (const float*)d_in[1];
    const float* W1 = (const float*)d_in[2];
    const float* b1 = (const float*)d_in[3];
    const float* W2 = (const float*)d_in[4];
    const float* b2 = (const float*)d_in[5];
    float* out = (float*)d_out;

    // dynamic smem: 512 + 3 * 35840 = 108032 B (2 CTAs/SM)
    constexpr int SMEM_SZ = 512 + 3 * 35840;
    static_assert(512 + 128 * (128 + 4) * 4 <= SMEM_SZ, "C reuse fits");
    cudaFuncSetAttribute((const void*)&expert_wmma<Dm, Hd, true,  true >,
                         cudaFuncAttributeMaxDynamicSharedMemorySize, SMEM_SZ);
    cudaFuncSetAttribute((const void*)&expert_wmma<Hd, Dm, false, false>,
                         cudaFuncAttributeMaxDynamicSharedMemorySize, SMEM_SZ);

    // DEVICE addresses of __device__ symbols (host-side symbol refs are invalid!)
    __half* xh;  cudaGetSymbolAddress((void**)&xh,  g_xh);
    __half* w1h; cudaGetSymbolAddress((void**)&w1h, g_w1h);
    __half* w2h; cudaGetSymbolAddress((void**)&w2h, g_w2h);

    // zero output (atomic accumulation target)
    zero_kernel<<<512, 256>>>(out, (size_t)Tt * Dm / 4);

    // 1) router (full-precision x) + fused x->fp16
    router_kernel<<<Tt / 8, 256>>>(x, Wr);
    // 2) exact ordered capacity dispatch (+ per-slot weights)
    scan_kernel<<<1, 1024>>>();
    // 2b) one-shot fp32 -> fp16 weight conversions
    f2h_kernel<<<2048, 256>>>(W1, w1h, (size_t)Ex * Dm * Hd / 8);
    f2h_kernel<<<2048, 256>>>(W2, w2h, (size_t)Ex * Hd * Dm / 8);
    // 3) GEMM1 + GELU: xh[gather] @ W1h + b1 -> g_h (fp16)
    expert_wmma<Dm, Hd, true,  true ><<<dim3(Hd / 128, Ex * (CAP / 128)), 256, SMEM_SZ>>>(
        xh, w1h, b1, nullptr);
    // 4) GEMM2 + fused weighted combine: g_h @ W2h + b2 -> atomicAdd out
    expert_wmma<Hd, Dm, false, false><<<dim3(Dm / 128, Ex * (CAP / 128)), 256, SMEM_SZ>>>(
        nullptr, w2h, b2, out);
}

// round 10
// speedup vs baseline: 1.1363x; 1.0411x over previous
#include <cuda_runtime.h>
#include <cuda_fp16.h>
#include <mma.h>
#include <math.h>
#include <stdint.h>

using namespace nvcuda;

// ---------------- problem constants ----------------
#define Dm 1024      // d_model
#define Hd 4096      // expert hidden
#define Ex 8         // experts
#define TK 2         // top-k
#define Bb 4
#define Ss 2048
#define Tt (Bb * Ss)         // 8192 tokens
#define PAIRS (Tt * TK)      // 16384
#define CAP 2560             // ceil(1.25 * T * K / E)

// ---------------- device scratch (no allocations allowed) ----------------
__device__ __half g_h  [(size_t)Ex * CAP * Hd];   // hidden acts (fp16)
__device__ float  g_eo [(size_t)Ex * CAP * Dm];   // expert outputs (fp32)
__device__ __half g_xh [(size_t)Tt * Dm];         // x in fp16
__device__ __half g_w1h[(size_t)Ex * Dm * Hd];    // W1 in fp16
__device__ __half g_w2h[(size_t)Ex * Hd * Dm];    // W2 in fp16
__device__ int    g_eid[PAIRS];
__device__ float  g_wp [PAIRS];
__device__ int    g_slot[PAIRS];
__device__ int    g_tok[Ex * CAP];
__device__ int    g_count[Ex];

// ---------------- helpers ----------------
__device__ __forceinline__ uint32_t smem_u32(const void* p) {
    uint32_t a;
    asm("{ .reg .u64 t; cvta.to.shared.u64 t, %1; cvt.u32.u64 %0, t; }" : "=r"(a) : "l"(p));
    return a;
}
__device__ __forceinline__ void cp16(uint32_t dst, const void* src) {
    asm volatile("cp.async.cg.shared.global [%0], [%1], 16;" :: "r"(dst), "l"(src));
}
#define CP_COMMIT() asm volatile("cp.async.commit_group;" ::: "memory")
#define CP_WAIT(n)  asm volatile("cp.async.wait_group %0;" :: "n"(n) : "memory")

// ---------------- router: warp per token (also emits x in fp16) ----------------
__global__ void router_kernel(const float* __restrict__ x,
                              const float* __restrict__ Wr)
{
    int warp = (blockIdx.x * blockDim.x + threadIdx.x) >> 5;
    int lane = threadIdx.x & 31;
    if (warp >= Tt) return;
    const float* xr = x + (size_t)warp * Dm;
    __half* xh = (__half*)g_xh + (size_t)warp * Dm;

    float acc[8];
#pragma unroll
    for (int e = 0; e < 8; e++) acc[e] = 0.f;
    for (int d = lane * 2; d < Dm; d += 64) {
        float2 xv = *(const float2*)(xr + d);
        *(__half2*)(xh + d) = __floats2half2_rn(xv.x, xv.y);
#pragma unroll
        for (int u = 0; u < 2; u++) {
            float xs = u ? xv.y : xv.x;
            const float4 a = *(const float4*)(Wr + (d + u) * 8);
            const float4 b = *(const float4*)(Wr + (d + u) * 8 + 4);
            acc[0] += xs * a.x; acc[1] += xs * a.y; acc[2] += xs * a.z; acc[3] += xs * a.w;
            acc[4] += xs * b.x; acc[5] += xs * b.y; acc[6] += xs * b.z; acc[7] += xs * b.w;
        }
    }
#pragma unroll
    for (int e = 0; e < 8; e++)
#pragma unroll
        for (int off = 16; off > 0; off >>= 1)
            acc[e] += __shfl_xor_sync(0xFFFFFFFFu, acc[e], off);
    if (lane == 0) {
        int e0 = 0; float l0 = acc[0];
#pragma unroll
        for (int e = 1; e < 8; e++) if (acc[e] > l0) { l0 = acc[e]; e0 = e; }
        int e1 = -1; float l1 = -3.4e38f;
#pragma unroll
        for (int e = 0; e < 8; e++) {
            if (e == e0) continue;
            if (acc[e] > l1) { l1 = acc[e]; e1 = e; }
        }
        float w0 = 1.0f / (1.0f + __expf(l1 - l0));
        g_eid[2 * warp + 0] = e0;  g_eid[2 * warp + 1] = e1;
        g_wp [2 * warp + 0] = w0;  g_wp [2 * warp + 1] = 1.0f - w0;
    }
}

// ---------------- exact ordered capacity dispatch (single block) ----------------
__global__ void scan_kernel()
{
    __shared__ int sc[8][1024];
    int tid = threadIdx.x;
    int base = tid * 16;

    int le[16]; int lc[8];
#pragma unroll
    for (int e = 0; e < 8; e++) lc[e] = 0;
#pragma unroll
    for (int i = 0; i < 16; i++) { le[i] = g_eid[base + i]; lc[le[i]]++; }
#pragma unroll
    for (int e = 0; e < 8; e++) sc[e][tid] = lc[e];
    __syncthreads();
    for (int off = 1; off < 1024; off <<= 1) {
        int v[8];
#pragma unroll
        for (int e = 0; e < 8; e++) v[e] = (tid >= off) ? sc[e][tid - off] : 0;
        __syncthreads();
#pragma unroll
        for (int e = 0; e < 8; e++) sc[e][tid] += v[e];
        __syncthreads();
    }
    int pos[8];
#pragma unroll
    for (int e = 0; e < 8; e++) pos[e] = sc[e][tid] - lc[e];
#pragma unroll
    for (int i = 0; i < 16; i++) {
        int e = le[i]; int p = pos[e]++; int pr = base + i;
        if (p < CAP) { int s = e * CAP + p; g_slot[pr] = s; g_tok[s] = pr >> 1; }
        else g_slot[pr] = -1;
    }
    if (tid < 8) { int c = sc[tid][1023]; g_count[tid] = (c < CAP) ? c : CAP; }
}

// ---------------- f32 -> f16 conversion (one-shot, vectorized x8) ----------------
__global__ void f2h_kernel(const float* __restrict__ src, __half* __restrict__ dst,
                           size_t n8)
{
    size_t i = (size_t)blockIdx.x * blockDim.x + threadIdx.x;
    size_t stride = (size_t)gridDim.x * blockDim.x;
    for (; i < n8; i += stride) {
        float4 a = ((const float4*)src)[2 * i + 0];
        float4 b = ((const float4*)src)[2 * i + 1];
        __half2 h[4];
        h[0] = __floats2half2_rn(a.x, a.y);
        h[1] = __floats2half2_rn(a.z, a.w);
        h[2] = __floats2half2_rn(b.x, b.y);
        h[3] = __floats2half2_rn(b.z, b.w);
        ((uint4*)dst)[i] = *(uint4*)h;
    }
}

// ---------------- GELU (tanh approx, matches jax.nn.gelu) ----------------
__device__ __forceinline__ float gelu_tanh(float v)
{
    float c = 0.7978845608028654f * (v + 0.044715f * v * v * v);
    return 0.5f * v * (1.0f + tanhf(c));
}

// ---------------- wmma fp16 expert GEMM, 64x64 warp tiles ----------------
// C[128x128] = act( A @ B + bias ).  128 threads / 4 warps, warp grid 2x2,
// warp tile 64x64, wmma 16x16x16 half, fp32 accum, BK=64, 3-stage cp.async.
template <int Kdim, int Ndim, bool GELU, bool GATHER>
__global__ void __launch_bounds__(128)
expert_wmma(const __half* __restrict__ Ax,
            const __half* __restrict__ Bw,
            const float* __restrict__ bias)
{
    constexpr int BM = 128, BN = 128, BK = 64, NS = 3;
    constexpr int MT = CAP / BM;              // 20 row tiles / expert
    constexpr int ASTh = BK + 8;              // 72 halfs
    constexpr int BSTh = BN + 8;              // 136 halfs
    constexpr int ABYTES = BM * ASTh * 2;     // 18432
    constexpr int BBYTES = BK * BSTh * 2;     // 17408
    constexpr int STAGE  = ABYTES + BBYTES;   // 35840
    constexpr int CST = BN + 4;

    extern __shared__ __align__(16) char smem[];
    int*   srow = (int*)smem;                  // 512 B
    float* sC   = (float*)(smem + 512);        // reused after mainloop
    char*  stg  = smem + 512;
    const uint32_t stg_u = smem_u32(stg);

    const int e   = blockIdx.y / MT;
    const int m0  = (blockIdx.y % MT) * BM;
    const int cnt = g_count[e];
    if (m0 >= cnt) return;
    const int n0  = blockIdx.x * BN;
    const int tid = threadIdx.x;
    const int wid = tid >> 5;

    {   // 128 threads fill 128-entry row table
        int r = m0 + tid;
        srow[tid] = (r < cnt) ? (GATHER ? g_tok[e * CAP + r] : e * CAP + r)
                              : (GATHER ? 0 : e * CAP);
    }
    __syncthreads();

    const __half* Asrc = GATHER ? Ax : (const __half*)g_h;
    const __half* Bexp = Bw + (size_t)e * Kdim * Ndim + n0;

    // A: 1024 16B chunks, 128 thr -> 8 each; row = chunk>>3, c8 = chunk&7
    const int ar0 = tid >> 3, ac8 = tid & 7;
    int arows[8];
#pragma unroll
    for (int l = 0; l < 8; l++) arows[l] = srow[ar0 + l * 16];
    // B: 1024 chunks; row = chunk>>4, c8 = chunk&15
    const int br0 = tid >> 4, bc8 = tid & 15;

    auto load_stage = [&](int s, int k0) {
        uint32_t sA = stg_u + s * STAGE;
        uint32_t sB = sA + ABYTES;
#pragma unroll
        for (int l = 0; l < 8; l++) {
            int row = ar0 + l * 16;
            cp16(sA + (uint32_t)(row * (ASTh * 2) + ac8 * 16),
                 Asrc + (size_t)arows[l] * Kdim + k0 + ac8 * 8);
        }
#pragma unroll
        for (int l = 0; l < 8; l++) {
            int row = br0 + l * 8;
            cp16(sB + (uint32_t)(row * (BSTh * 2) + bc8 * 16),
                 Bexp + (size_t)(k0 + row) * Ndim + bc8 * 8);
        }
        CP_COMMIT();
    };

    const int warp_m = wid >> 1;     // 0..1 -> rows warp_m*64
    const int warp_n = wid & 1;      // 0..1 -> cols warp_n*64

    wmma::fragment<wmma::accumulator, 16, 16, 16, float> acc[4][4];
#pragma unroll
    for (int i = 0; i < 4; i++)
#pragma unroll
        for (int j = 0; j < 4; j++) wmma::fill_fragment(acc[i][j], 0.f);

    constexpr int KT = Kdim / BK;
    load_stage(0, 0);
    load_stage(1, BK);

    int cs = 0;
    for (int j = 0; j < KT; j++) {
        if (j + 2 < KT) CP_WAIT(1); else CP_WAIT(0);
        __syncthreads();
        if (j + 2 < KT) {
            int ls = cs + 2; if (ls >= NS) ls -= NS;
            load_stage(ls, (j + 2) * BK);
        }

        const __half* sA = (const __half*)(stg + cs * STAGE);
        const __half* sB = (const __half*)(stg + cs * STAGE + ABYTES);

#pragma unroll
        for (int ks = 0; ks < BK / 16; ks++) {
            wmma::fragment<wmma::matrix_a, 16, 16, 16, __half, wmma::row_major> af[4];
#pragma unroll
            for (int i = 0; i < 4; i++)
                wmma::load_matrix_sync(af[i], sA + (warp_m * 64 + i * 16) * ASTh + ks * 16, ASTh);
#pragma unroll
            for (int jn = 0; jn < 4; jn++) {
                wmma::fragment<wmma::matrix_b, 16, 16, 16, __half, wmma::row_major> bf;
                wmma::load_matrix_sync(bf, sB + (ks * 16) * BSTh + warp_n * 64 + jn * 16, BSTh);
#pragma unroll
                for (int i = 0; i < 4; i++)
                    wmma::mma_sync(acc[i][jn], af[i], bf, acc[i][jn]);
            }
        }
        cs++; if (cs >= NS) cs = 0;
    }

    __syncthreads();

#pragma unroll
    for (int i = 0; i < 4; i++)
#pragma unroll
        for (int jn = 0; jn < 4; jn++)
            wmma::store_matrix_sync(sC + (warp_m * 64 + i * 16) * CST + warp_n * 64 + jn * 16,
                                    acc[i][jn], CST, wmma::mem_row_major);
    __syncthreads();

    // epilogue: 1 thread per row, 128 cols
    {
        const int row = tid;
        const int r = m0 + row;
        if (r < cnt) {
            const float* bv = bias + e * Ndim + n0;
            const float* src = sC + row * CST;
            if (GELU) {
                __half* crow = (__half*)g_h + ((size_t)(e * CAP + r)) * Ndim + n0;
#pragma unroll
                for (int c = 0; c < BN; c += 4) {
                    float4 v = *(const float4*)(src + c);
                    v.x = gelu_tanh(v.x + __ldg(bv + c + 0));
                    v.y = gelu_tanh(v.y + __ldg(bv + c + 1));
                    v.z = gelu_tanh(v.z + __ldg(bv + c + 2));
                    v.w = gelu_tanh(v.w + __ldg(bv + c + 3));
                    __half2 h0 = __floats2half2_rn(v.x, v.y);
                    __half2 h1 = __floats2half2_rn(v.z, v.w);
                    *(uint2*)(crow + c) = make_uint2(*(uint32_t*)&h0, *(uint32_t*)&h1);
                }
            } else {
                float* crow = g_eo + ((size_t)(e * CAP + r)) * Ndim + n0;
#pragma unroll
                for (int c = 0; c < BN; c += 4) {
                    float4 v = *(const float4*)(src + c);
                    v.x += __ldg(bv + c + 0);
                    v.y += __ldg(bv + c + 1);
                    v.z += __ldg(bv + c + 2);
                    v.w += __ldg(bv + c + 3);
                    *(float4*)(crow + c) = v;
                }
            }
        }
    }
}

// ---------------- combine: one block per token ----------------
__global__ void combine_kernel(float* __restrict__ out)
{
    int t = blockIdx.x;
    int c = threadIdx.x * 4;
    int   s0 = g_slot[2 * t + 0];
    int   s1 = g_slot[2 * t + 1];
    float w0 = g_wp[2 * t + 0];
    float w1 = g_wp[2 * t + 1];
    float4 r = make_float4(0.f, 0.f, 0.f, 0.f);
    if (s0 >= 0) {
        float4 a = *(const float4*)(g_eo + (size_t)s0 * Dm + c);
        r.x += w0 * a.x; r.y += w0 * a.y; r.z += w0 * a.z; r.w += w0 * a.w;
    }
    if (s1 >= 0) {
        float4 a = *(const float4*)(g_eo + (size_t)s1 * Dm + c);
        r.x += w1 * a.x; r.y += w1 * a.y; r.z += w1 * a.z; r.w += w1 * a.w;
    }
    *(float4*)(out + (size_t)t * Dm + c) = r;
}

// ---------------- entry point ----------------
extern "C" void kernel_launch(void* const* d_in, const int* in_sizes, int n_in,
                              void* d_out, int out_size)
{
    const float* x  = (const float*)d_in[0];
    const float* Wr = (const float*)d_in[1];
    const float* W1 = (const float*)d_in[2];
    const float* b1 = (const float*)d_in[3];
    const float* W2 = (const float*)d_in[4];
    const float* b2 = (const float*)d_in[5];
    float* out = (float*)d_out;

    // dynamic smem: 512 + 3 * 35840 = 108032 B (2 CTAs/SM by smem)
    constexpr int SMEM_SZ = 512 + 3 * 35840;
    static_assert(512 + 128 * (128 + 4) * 4 <= SMEM_SZ, "C reuse fits");
    cudaFuncSetAttribute((const void*)&expert_wmma<Dm, Hd, true,  true >,
                         cudaFuncAttributeMaxDynamicSharedMemorySize, SMEM_SZ);
    cudaFuncSetAttribute((const void*)&expert_wmma<Hd, Dm, false, false>,
                         cudaFuncAttributeMaxDynamicSharedMemorySize, SMEM_SZ);

    // device addresses of __device__ symbols
    __half* xh;  cudaGetSymbolAddress((void**)&xh,  g_xh);
    __half* w1h; cudaGetSymbolAddress((void**)&w1h, g_w1h);
    __half* w2h; cudaGetSymbolAddress((void**)&w2h, g_w2h);

    // 1) router + fused x->fp16
    router_kernel<<<Tt / 8, 256>>>(x, Wr);
    // 2) exact ordered capacity dispatch
    scan_kernel<<<1, 1024>>>();
    // 2b) one-shot fp32 -> fp16 weight conversions
    f2h_kernel<<<2048, 256>>>(W1, w1h, (size_t)Ex * Dm * Hd / 8);
    f2h_kernel<<<2048, 256>>>(W2, w2h, (size_t)Ex * Hd * Dm / 8);
    // 3) GEMM1 + GELU: xh[gather] @ W1h + b1 -> g_h (fp16)
    expert_wmma<Dm, Hd, true,  true ><<<dim3(Hd / 128, Ex * (CAP / 128)), 128, SMEM_SZ>>>(xh, w1h, b1);
    // 4) GEMM2: g_h @ W2h + b2 -> g_eo (fp32)
    expert_wmma<Hd, Dm, false, false><<<dim3(Dm / 128, Ex * (CAP / 128)), 128, SMEM_SZ>>>(nullptr, w2h, b2);
    // 5) combine
    combine_kernel<<<Tt, 256>>>(out);
}

// round 11
// speedup vs baseline: 1.1645x; 1.0249x over previous
#include <cuda_runtime.h>
#include <cuda_fp16.h>
#include <mma.h>
#include <math.h>
#include <stdint.h>

using namespace nvcuda;

// ---------------- problem constants ----------------
#define Dm 1024      // d_model
#define Hd 4096      // expert hidden
#define Ex 8         // experts
#define TK 2         // top-k
#define Bb 4
#define Ss 2048
#define Tt (Bb * Ss)         // 8192 tokens
#define PAIRS (Tt * TK)      // 16384
#define CAP 2560             // ceil(1.25 * T * K / E)

// ---------------- device scratch (no allocations allowed) ----------------
__device__ __half g_h  [(size_t)Ex * CAP * Hd];   // hidden acts (fp16)
__device__ __half g_eo [(size_t)Ex * CAP * Dm];   // expert outputs (fp16)
__device__ __half g_xh [(size_t)Tt * Dm];         // x in fp16
__device__ __half g_w1h[(size_t)Ex * Dm * Hd];    // W1 in fp16
__device__ __half g_w2h[(size_t)Ex * Hd * Dm];    // W2 in fp16
__device__ int    g_eid[PAIRS];
__device__ float  g_wp [PAIRS];
__device__ int    g_slot[PAIRS];
__device__ int    g_tok[Ex * CAP];
__device__ int    g_count[Ex];

// ---------------- helpers ----------------
__device__ __forceinline__ uint32_t smem_u32(const void* p) {
    uint32_t a;
    asm("{ .reg .u64 t; cvta.to.shared.u64 t, %1; cvt.u32.u64 %0, t; }" : "=r"(a) : "l"(p));
    return a;
}
__device__ __forceinline__ void cp16(uint32_t dst, const void* src) {
    asm volatile("cp.async.cg.shared.global [%0], [%1], 16;" :: "r"(dst), "l"(src));
}
#define CP_COMMIT() asm volatile("cp.async.commit_group;" ::: "memory")
#define CP_WAIT(n)  asm volatile("cp.async.wait_group %0;" :: "n"(n) : "memory")

__device__ __forceinline__ void f2h8(const float* __restrict__ src, __half* __restrict__ dst,
                                     size_t i)
{
    float4 a = ((const float4*)src)[2 * i + 0];
    float4 b = ((const float4*)src)[2 * i + 1];
    __half2 h[4];
    h[0] = __floats2half2_rn(a.x, a.y);
    h[1] = __floats2half2_rn(a.z, a.w);
    h[2] = __floats2half2_rn(b.x, b.y);
    h[3] = __floats2half2_rn(b.z, b.w);
    ((uint4*)dst)[i] = *(uint4*)h;
}

// ---------------- router: warp per token (also emits x in fp16) ----------------
__global__ void router_kernel(const float* __restrict__ x,
                              const float* __restrict__ Wr)
{
    int warp = (blockIdx.x * blockDim.x + threadIdx.x) >> 5;
    int lane = threadIdx.x & 31;
    if (warp >= Tt) return;
    const float* xr = x + (size_t)warp * Dm;
    __half* xh = (__half*)g_xh + (size_t)warp * Dm;

    float acc[8];
#pragma unroll
    for (int e = 0; e < 8; e++) acc[e] = 0.f;
    for (int d = lane * 2; d < Dm; d += 64) {
        float2 xv = *(const float2*)(xr + d);
        *(__half2*)(xh + d) = __floats2half2_rn(xv.x, xv.y);
#pragma unroll
        for (int u = 0; u < 2; u++) {
            float xs = u ? xv.y : xv.x;
            const float4 a = *(const float4*)(Wr + (d + u) * 8);
            const float4 b = *(const float4*)(Wr + (d + u) * 8 + 4);
            acc[0] += xs * a.x; acc[1] += xs * a.y; acc[2] += xs * a.z; acc[3] += xs * a.w;
            acc[4] += xs * b.x; acc[5] += xs * b.y; acc[6] += xs * b.z; acc[7] += xs * b.w;
        }
    }
#pragma unroll
    for (int e = 0; e < 8; e++)
#pragma unroll
        for (int off = 16; off > 0; off >>= 1)
            acc[e] += __shfl_xor_sync(0xFFFFFFFFu, acc[e], off);
    if (lane == 0) {
        int e0 = 0; float l0 = acc[0];
#pragma unroll
        for (int e = 1; e < 8; e++) if (acc[e] > l0) { l0 = acc[e]; e0 = e; }
        int e1 = -1; float l1 = -3.4e38f;
#pragma unroll
        for (int e = 0; e < 8; e++) {
            if (e == e0) continue;
            if (acc[e] > l1) { l1 = acc[e]; e1 = e; }
        }
        float w0 = 1.0f / (1.0f + __expf(l1 - l0));
        g_eid[2 * warp + 0] = e0;  g_eid[2 * warp + 1] = e1;
        g_wp [2 * warp + 0] = w0;  g_wp [2 * warp + 1] = 1.0f - w0;
    }
}

// ---------------- exact ordered capacity dispatch (single block) ----------------
__global__ void scan_kernel()
{
    __shared__ int sc[8][1024];
    int tid = threadIdx.x;
    int base = tid * 16;

    int le[16]; int lc[8];
#pragma unroll
    for (int e = 0; e < 8; e++) lc[e] = 0;
#pragma unroll
    for (int i = 0; i < 16; i++) { le[i] = g_eid[base + i]; lc[le[i]]++; }
#pragma unroll
    for (int e = 0; e < 8; e++) sc[e][tid] = lc[e];
    __syncthreads();
    for (int off = 1; off < 1024; off <<= 1) {
        int v[8];
#pragma unroll
        for (int e = 0; e < 8; e++) v[e] = (tid >= off) ? sc[e][tid - off] : 0;
        __syncthreads();
#pragma unroll
        for (int e = 0; e < 8; e++) sc[e][tid] += v[e];
        __syncthreads();
    }
    int pos[8];
#pragma unroll
    for (int e = 0; e < 8; e++) pos[e] = sc[e][tid] - lc[e];
#pragma unroll
    for (int i = 0; i < 16; i++) {
        int e = le[i]; int p = pos[e]++; int pr = base + i;
        if (p < CAP) { int s = e * CAP + p; g_slot[pr] = s; g_tok[s] = pr >> 1; }
        else g_slot[pr] = -1;
    }
    if (tid < 8) { int c = sc[tid][1023]; g_count[tid] = (c < CAP) ? c : CAP; }
}

// ---------------- f32 -> f16 conversion (standalone, for W1) ----------------
__global__ void f2h_kernel(const float* __restrict__ src, __half* __restrict__ dst,
                           size_t n8)
{
    size_t i = (size_t)blockIdx.x * blockDim.x + threadIdx.x;
    size_t stride = (size_t)gridDim.x * blockDim.x;
    for (; i < n8; i += stride) f2h8(src, dst, i);
}

// ---------------- GELU (tanh approx, matches jax.nn.gelu) ----------------
__device__ __forceinline__ float gelu_tanh(float v)
{
    float c = 0.7978845608028654f * (v + 0.044715f * v * v * v);
    return 0.5f * v * (1.0f + tanhf(c));
}

// ---------------- wmma fp16 expert GEMM (R6 config) ----------------
// C[128x128] = act( A @ B + bias ).  8 warps, warp tile 32x64, BK=64,
// 3-stage cp.async, 2 CTAs/SM.  In the GELU (GEMM1) instantiation the extra
// blockIdx.x slice converts W2 fp32->fp16 concurrently (HBM is idle there).
template <int Kdim, int Ndim, bool GELU, bool GATHER>
__global__ void __launch_bounds__(256, 2)
expert_wmma(const __half* __restrict__ Ax,
            const __half* __restrict__ Bw,
            const float* __restrict__ bias,
            const float* __restrict__ cvt_src,   // W2 fp32 (GEMM1 only)
            __half* __restrict__ cvt_dst)        // W2 fp16 (GEMM1 only)
{
    constexpr int BM = 128, BN = 128, BK = 64, NS = 3;
    constexpr int MT = CAP / BM;              // 20 row tiles / expert
    constexpr int ASTh = BK + 8;
    constexpr int BSTh = BN + 8;
    constexpr int ABYTES = BM * ASTh * 2;     // 18432
    constexpr int BBYTES = BK * BSTh * 2;     // 17408
    constexpr int STAGE  = ABYTES + BBYTES;   // 35840
    constexpr int CST = BN + 4;

    // side-job blocks: convert W2 while GEMM1's tensor pipe owns the SMs
    if (GELU && blockIdx.x == Ndim / BN) {
        const size_t n8 = (size_t)Ex * Hd * Dm / 8;
        size_t i = (size_t)blockIdx.y * blockDim.x + threadIdx.x;
        const size_t stride = (size_t)gridDim.y * blockDim.x;
        for (; i < n8; i += stride) f2h8(cvt_src, cvt_dst, i);
        return;
    }

    extern __shared__ __align__(16) char smem[];
    int*   srow = (int*)smem;
    float* sC   = (float*)(smem + 512);
    char*  stg  = smem + 512;
    const uint32_t stg_u = smem_u32(stg);

    const int e   = blockIdx.y / MT;
    const int m0  = (blockIdx.y % MT) * BM;
    const int cnt = g_count[e];
    if (m0 >= cnt) return;
    const int n0  = blockIdx.x * BN;
    const int tid = threadIdx.x;
    const int wid = tid >> 5;

    if (tid < BM) {
        int r = m0 + tid;
        srow[tid] = (r < cnt) ? (GATHER ? g_tok[e * CAP + r] : e * CAP + r)
                              : (GATHER ? 0 : e * CAP);
    }
    __syncthreads();

    const __half* Asrc = GATHER ? Ax : (const __half*)g_h;
    const __half* Bexp = Bw + (size_t)e * Kdim * Ndim + n0;

    const int ar0 = tid >> 3, ac8 = tid & 7;
    int arows[4];
#pragma unroll
    for (int l = 0; l < 4; l++) arows[l] = srow[ar0 + l * 32];
    const int br0 = tid >> 4, bc8 = tid & 15;

    auto load_stage = [&](int s, int k0) {
        uint32_t sA = stg_u + s * STAGE;
        uint32_t sB = sA + ABYTES;
#pragma unroll
        for (int l = 0; l < 4; l++) {
            int row = ar0 + l * 32;
            cp16(sA + (uint32_t)(row * (ASTh * 2) + ac8 * 16),
                 Asrc + (size_t)arows[l] * Kdim + k0 + ac8 * 8);
        }
#pragma unroll
        for (int l = 0; l < 4; l++) {
            int row = br0 + l * 16;
            cp16(sB + (uint32_t)(row * (BSTh * 2) + bc8 * 16),
                 Bexp + (size_t)(k0 + row) * Ndim + bc8 * 8);
        }
        CP_COMMIT();
    };

    const int warp_m = wid >> 1;
    const int warp_n = wid & 1;

    wmma::fragment<wmma::accumulator, 16, 16, 16, float> acc[2][4];
#pragma unroll
    for (int i = 0; i < 2; i++)
#pragma unroll
        for (int j = 0; j < 4; j++) wmma::fill_fragment(acc[i][j], 0.f);

    constexpr int KT = Kdim / BK;
    load_stage(0, 0);
    load_stage(1, BK);

    int cs = 0;
    for (int j = 0; j < KT; j++) {
        if (j + 2 < KT) CP_WAIT(1); else CP_WAIT(0);
        __syncthreads();
        if (j + 2 < KT) {
            int ls = cs + 2; if (ls >= NS) ls -= NS;
            load_stage(ls, (j + 2) * BK);
        }

        const __half* sA = (const __half*)(stg + cs * STAGE);
        const __half* sB = (const __half*)(stg + cs * STAGE + ABYTES);

#pragma unroll
        for (int ks = 0; ks < BK / 16; ks++) {
            wmma::fragment<wmma::matrix_a, 16, 16, 16, __half, wmma::row_major> af[2];
            wmma::fragment<wmma::matrix_b, 16, 16, 16, __half, wmma::row_major> bf[4];
#pragma unroll
            for (int i = 0; i < 2; i++)
                wmma::load_matrix_sync(af[i], sA + (warp_m * 32 + i * 16) * ASTh + ks * 16, ASTh);
#pragma unroll
            for (int jn = 0; jn < 4; jn++)
                wmma::load_matrix_sync(bf[jn], sB + (ks * 16) * BSTh + warp_n * 64 + jn * 16, BSTh);
#pragma unroll
            for (int i = 0; i < 2; i++)
#pragma unroll
                for (int jn = 0; jn < 4; jn++)
                    wmma::mma_sync(acc[i][jn], af[i], bf[jn], acc[i][jn]);
        }
        cs++; if (cs >= NS) cs = 0;
    }

    __syncthreads();

#pragma unroll
    for (int i = 0; i < 2; i++)
#pragma unroll
        for (int jn = 0; jn < 4; jn++)
            wmma::store_matrix_sync(sC + (warp_m * 32 + i * 16) * CST + warp_n * 64 + jn * 16,
                                    acc[i][jn], CST, wmma::mem_row_major);
    __syncthreads();

    // epilogue: 2 threads per row, 64 cols each; fp16 outputs both ways
    {
        const int row  = tid >> 1;
        const int col0 = (tid & 1) * 64;
        const int r = m0 + row;
        if (r < cnt) {
            const float* bv = bias + e * Ndim + n0 + col0;
            const float* src = sC + row * CST + col0;
            __half* crow = (GELU ? (__half*)g_h : (__half*)g_eo)
                           + ((size_t)(e * CAP + r)) * Ndim + n0 + col0;
#pragma unroll
            for (int c = 0; c < 64; c += 4) {
                float4 v = *(const float4*)(src + c);
                v.x += __ldg(bv + c + 0);
                v.y += __ldg(bv + c + 1);
                v.z += __ldg(bv + c + 2);
                v.w += __ldg(bv + c + 3);
                if (GELU) {
                    v.x = gelu_tanh(v.x); v.y = gelu_tanh(v.y);
                    v.z = gelu_tanh(v.z); v.w = gelu_tanh(v.w);
                }
                __half2 h0 = __floats2half2_rn(v.x, v.y);
                __half2 h1 = __floats2half2_rn(v.z, v.w);
                *(uint2*)(crow + c) = make_uint2(*(uint32_t*)&h0, *(uint32_t*)&h1);
            }
        }
    }
}

// ---------------- combine: one block per token (fp16 expert outputs) ----------
__global__ void combine_kernel(float* __restrict__ out)
{
    int t = blockIdx.x;
    int c = threadIdx.x * 4;   // 256 threads * 4 = 1024
    int   s0 = g_slot[2 * t + 0];
    int   s1 = g_slot[2 * t + 1];
    float w0 = g_wp[2 * t + 0];
    float w1 = g_wp[2 * t + 1];
    float4 r = make_float4(0.f, 0.f, 0.f, 0.f);
    if (s0 >= 0) {
        uint2 p = *(const uint2*)((const __half*)g_eo + (size_t)s0 * Dm + c);
        float2 a0 = __half22float2(*(__half2*)&p.x);
        float2 a1 = __half22float2(*(__half2*)&p.y);
        r.x += w0 * a0.x; r.y += w0 * a0.y; r.z += w0 * a1.x; r.w += w0 * a1.y;
    }
    if (s1 >= 0) {
        uint2 p = *(const uint2*)((const __half*)g_eo + (size_t)s1 * Dm + c);
        float2 a0 = __half22float2(*(__half2*)&p.x);
        float2 a1 = __half22float2(*(__half2*)&p.y);
        r.x += w1 * a0.x; r.y += w1 * a0.y; r.z += w1 * a1.x; r.w += w1 * a1.y;
    }
    *(float4*)(out + (size_t)t * Dm + c) = r;
}

// ---------------- entry point ----------------
extern "C" void kernel_launch(void* const* d_in, const int* in_sizes, int n_in,
                              void* d_out, int out_size)
{
    const float* x  = (const float*)d_in[0];
    const float* Wr = (const float*)d_in[1];
    const float* W1 = (const float*)d_in[2];
    const float* b1 = (const float*)d_in[3];
    const float* W2 = (const float*)d_in[4];
    const float* b2 = (const float*)d_in[5];
    float* out = (float*)d_out;

    // dynamic smem: 512 + 3 * 35840 = 108032 B (2 CTAs/SM)
    constexpr int SMEM_SZ = 512 + 3 * 35840;
    static_assert(512 + 128 * (128 + 4) * 4 <= SMEM_SZ, "C reuse fits");
    cudaFuncSetAttribute((const void*)&expert_wmma<Dm, Hd, true,  true >,
                         cudaFuncAttributeMaxDynamicSharedMemorySize, SMEM_SZ);
    cudaFuncSetAttribute((const void*)&expert_wmma<Hd, Dm, false, false>,
                         cudaFuncAttributeMaxDynamicSharedMemorySize, SMEM_SZ);

    // device addresses of __device__ symbols
    __half* xh;  cudaGetSymbolAddress((void**)&xh,  g_xh);
    __half* w1h; cudaGetSymbolAddress((void**)&w1h, g_w1h);
    __half* w2h; cudaGetSymbolAddress((void**)&w2h, g_w2h);

    // 1) router + fused x->fp16
    router_kernel<<<Tt / 8, 256>>>(x, Wr);
    // 2) exact ordered capacity dispatch
    scan_kernel<<<1, 1024>>>();
    // 2b) W1 fp32 -> fp16 (W2 conversion rides inside GEMM1)
    f2h_kernel<<<2048, 256>>>(W1, w1h, (size_t)Ex * Dm * Hd / 8);
    // 3) GEMM1 + GELU (+ concurrent W2 f2h in the extra x-slice)
    expert_wmma<Dm, Hd, true,  true ><<<dim3(Hd / 128 + 1, Ex * (CAP / 128)), 256, SMEM_SZ>>>(
        xh, w1h, b1, W2, w2h);
    // 4) GEMM2: g_h @ W2h + b2 -> g_eo (fp16)
    expert_wmma<Hd, Dm, false, false><<<dim3(Dm / 128, Ex * (CAP / 128)), 256, SMEM_SZ>>>(
        nullptr, w2h, b2, nullptr, nullptr);
    // 5) combine
    combine_kernel<<<Tt, 256>>>(out);
}